// round 2
// baseline (speedup 1.0000x reference)
#include <cuda_runtime.h>

#define B_   64
#define LX_  512
#define LY_  512
#define DIM_ 64
#define BIGF 1e30f

// Diagonal-major scratch: g_Dt[b][t][i] = D[b][i][t - i], t in [0, 1023)
__device__ float g_Dt[(size_t)B_ * 1024 * 512];

typedef unsigned long long u64;

__device__ __forceinline__ u64 pack2(float lo, float hi) {
    u64 r; asm("mov.b64 %0,{%1,%2};" : "=l"(r) : "f"(lo), "f"(hi)); return r;
}
__device__ __forceinline__ u64 ffma2(u64 a, u64 b, u64 c) {
    u64 d; asm("fma.rn.f32x2 %0,%1,%2,%3;" : "=l"(d) : "l"(a), "l"(b), "l"(c)); return d;
}
__device__ __forceinline__ float2 unpack2(u64 v) {
    float2 f; asm("mov.b64 {%0,%1},%2;" : "=f"(f.x), "=f"(f.y) : "l"(v)); return f;
}

// ---------------------------------------------------------------------------
// Kernel 1: batched pairwise squared-L2 "GEMM", 64x64 tiles, 256 threads,
// 4x4 micro-tiles with packed f32x2 FMAs, diagonal-major writeout.
// ---------------------------------------------------------------------------
__global__ __launch_bounds__(256) void sdtw_gemm_kernel(
    const float* __restrict__ X, const float* __restrict__ Y)
{
    __shared__ float Xs[DIM_][68];   // k-major: Xs[k][i_local]
    __shared__ float Ys[DIM_][68];   // k-major: Ys[k][j_local]
    __shared__ float sx2[64];
    __shared__ float sy2[64];

    const int b  = blockIdx.z;
    const int i0 = blockIdx.y * 64;
    const int j0 = blockIdx.x * 64;
    const int tid = threadIdx.x;

    const float* Xb = X + ((size_t)b * LX_ + i0) * DIM_;
    const float* Yb = Y + ((size_t)b * LY_ + j0) * DIM_;

#pragma unroll
    for (int it = 0; it < 4; ++it) {
        int linear = it * 256 + tid;      // 0..1023
        int row = linear >> 4;            // 0..63
        int k4  = (linear & 15) << 2;     // 0..60
        float4 xv = *(const float4*)(Xb + row * DIM_ + k4);
        Xs[k4 + 0][row] = xv.x; Xs[k4 + 1][row] = xv.y;
        Xs[k4 + 2][row] = xv.z; Xs[k4 + 3][row] = xv.w;
        float4 yv = *(const float4*)(Yb + row * DIM_ + k4);
        Ys[k4 + 0][row] = yv.x; Ys[k4 + 1][row] = yv.y;
        Ys[k4 + 2][row] = yv.z; Ys[k4 + 3][row] = yv.w;
    }
    __syncthreads();

    if (tid < 64) {
        float v = 0.f;
#pragma unroll 8
        for (int k = 0; k < DIM_; ++k) v = fmaf(Xs[k][tid], Xs[k][tid], v);
        sx2[tid] = v;
    } else if (tid < 128) {
        int j = tid - 64;
        float v = 0.f;
#pragma unroll 8
        for (int k = 0; k < DIM_; ++k) v = fmaf(Ys[k][j], Ys[k][j], v);
        sy2[j] = v;
    }
    __syncthreads();

    const int tx = tid & 15;   // j
    const int ty = tid >> 4;   // i

    // Packed accumulators: acc2[r][0] = {dot(r, c0), dot(r, c1)}, etc.
    u64 acc2[4][2];
    const u64 z = pack2(0.f, 0.f);
#pragma unroll
    for (int r = 0; r < 4; ++r) { acc2[r][0] = z; acc2[r][1] = z; }

#pragma unroll 8
    for (int k = 0; k < DIM_; ++k) {
        float4 xv = *(const float4*)&Xs[k][ty * 4];
        const u64* yp = (const u64*)&Ys[k][tx * 4];
        u64 y01 = yp[0];
        u64 y23 = yp[1];
        u64 xp0 = pack2(xv.x, xv.x);
        u64 xp1 = pack2(xv.y, xv.y);
        u64 xp2 = pack2(xv.z, xv.z);
        u64 xp3 = pack2(xv.w, xv.w);
        acc2[0][0] = ffma2(xp0, y01, acc2[0][0]);
        acc2[0][1] = ffma2(xp0, y23, acc2[0][1]);
        acc2[1][0] = ffma2(xp1, y01, acc2[1][0]);
        acc2[1][1] = ffma2(xp1, y23, acc2[1][1]);
        acc2[2][0] = ffma2(xp2, y01, acc2[2][0]);
        acc2[2][1] = ffma2(xp2, y23, acc2[2][1]);
        acc2[3][0] = ffma2(xp3, y01, acc2[3][0]);
        acc2[3][1] = ffma2(xp3, y23, acc2[3][1]);
    }

    // d = x2 + y2 - 2*dot
    float dres[4][4];
#pragma unroll
    for (int r = 0; r < 4; ++r) {
        float xr2 = sx2[ty * 4 + r];
        float2 a01 = unpack2(acc2[r][0]);
        float2 a23 = unpack2(acc2[r][1]);
        dres[r][0] = fmaf(-2.0f, a01.x, xr2 + sy2[tx * 4 + 0]);
        dres[r][1] = fmaf(-2.0f, a01.y, xr2 + sy2[tx * 4 + 1]);
        dres[r][2] = fmaf(-2.0f, a23.x, xr2 + sy2[tx * 4 + 2]);
        dres[r][3] = fmaf(-2.0f, a23.y, xr2 + sy2[tx * 4 + 3]);
    }

    __syncthreads();  // done reading Xs/Ys; alias as stage

    // Stage tile: pitch 66 -> anti-diagonal stride 65 (conflict-free).
    float* Cs = &Xs[0][0];
    const int CP = 66;
#pragma unroll
    for (int r = 0; r < 4; ++r)
#pragma unroll
        for (int c = 0; c < 4; ++c)
            Cs[(ty * 4 + r) * CP + (tx * 4 + c)] = dres[r][c];
    __syncthreads();

    // Writeout along anti-diagonals: Dt[b][i0+j0+tl][i0+li]
    float* Dtb = g_Dt + (size_t)b * (1024 * 512) + (size_t)(i0 + j0) * 512 + i0;
    const int g  = tid >> 6;
    const int li = tid & 63;
    for (int tl = g; tl < 127; tl += 4) {
        int ilo = tl - 63; if (ilo < 0) ilo = 0;
        int ihi = tl;      if (ihi > 63) ihi = 63;
        if (li >= ilo && li <= ihi) {
            Dtb[(size_t)tl * 512 + li] = Cs[li * (CP - 1) + tl];
        }
    }
}

// ---------------------------------------------------------------------------
// Kernel 2: soft-DTW wavefront. One CTA per batch, one thread per row.
// 8-deep register prefetch ring for D; double-buffered float2(r1,r2) smem
// ring with BIG sentinel; one __syncthreads per diagonal.
// ---------------------------------------------------------------------------
__global__ __launch_bounds__(512) void sdtw_dp_kernel(float* __restrict__ out)
{
    __shared__ float2 rbuf[2][LX_ + 1];

    const int i = threadIdx.x;
    const int b = blockIdx.x;
    const float* __restrict__ Db = g_Dt + (size_t)b * (1024 * 512) + i;

    rbuf[0][i + 1] = make_float2(BIGF, BIGF);
    rbuf[1][i + 1] = make_float2(BIGF, BIGF);
    if (i == 0) {
        rbuf[0][0] = make_float2(BIGF, BIGF);
        rbuf[1][0] = make_float2(BIGF, BIGF);
    }

    float rp1 = BIGF;      // my r1[i]
    float dreg[8];         // statically-indexed prefetch ring, depth 8
#pragma unroll
    for (int u = 0; u < 8; ++u) dreg[u] = __ldg(Db + (size_t)u * 512);
    __syncthreads();

    const int TMAX = LX_ + LY_ - 1;   // 1023

#pragma unroll 1
    for (int tb = 0; tb < 1024; tb += 8) {
#pragma unroll
        for (int u = 0; u < 8; ++u) {
            int t = tb + u;
            if (t < TMAX) {                        // uniform across CTA
                float dcur = dreg[u];
                int tp = t + 8; if (tp > TMAX - 1) tp = TMAX - 1;
                dreg[u] = __ldg(Db + (size_t)tp * 512);   // prefetch 8 ahead

                float2 nb = rbuf[(t + 1) & 1][i];  // r1[i-1], r2[i-1]
                float up = nb.x;
                float dg = nb.y;
                if (i == 0 && t == 0) dg = 0.0f;   // origin

                int j = t - i;
                float lf = (j >= 1) ? rp1 : BIGF;

                float m = fminf(dg, fminf(up, lf));
                float s = __expf(m - dg) + __expf(m - up) + __expf(m - lf);
                float smin = m - __logf(s);        // gamma = 1

                float rc = ((unsigned)j < (unsigned)LY_) ? (dcur + smin) : BIGF;

                rbuf[t & 1][i + 1] = make_float2(rc, rp1);
                rp1 = rc;
                __syncthreads();
            }
        }
    }

    if (i == LX_ - 1) out[b] = rp1;
}

// ---------------------------------------------------------------------------
extern "C" void kernel_launch(void* const* d_in, const int* in_sizes, int n_in,
                              void* d_out, int out_size)
{
    (void)in_sizes; (void)n_in; (void)out_size;
    const float* X = (const float*)d_in[0];
    const float* Y = (const float*)d_in[1];
    float* out = (float*)d_out;

    dim3 gg(LY_ / 64, LX_ / 64, B_);
    sdtw_gemm_kernel<<<gg, 256>>>(X, Y);
    sdtw_dp_kernel<<<B_, LX_>>>(out);
}